// round 10
// baseline (speedup 1.0000x reference)
#include <cuda_runtime.h>
#include <cuda_fp16.h>
#include <cstdint>

#define HID 128
#define NNODES 100000

// Node projections, fp16: P[node][0:128] = x@W1[0:128], [128:256] = x@W1[128:256]
__device__ __half g_Ph[(size_t)NNODES * 256];
// W1 packed into fp16 m16n8k16 B-fragment order: [2 halves][8 kc][16 nf][32 lanes] uint2
__device__ uint2 g_W1fh[2 * 8 * 16 * 32];

// ----------------------------------------------------------------------------
// mma helper (portable: sm_103 PTX target has no tcgen05)
// fp16: D[16x8] += A[16x16] * B[16x8], fp32 accum
// ----------------------------------------------------------------------------
__device__ __forceinline__ void mma_f16(float* d, const uint32_t* a, uint32_t b0, uint32_t b1) {
    asm volatile(
        "mma.sync.aligned.m16n8k16.row.col.f32.f16.f16.f32 "
        "{%0,%1,%2,%3}, {%4,%5,%6,%7}, {%8,%9}, {%0,%1,%2,%3};"
        : "+f"(d[0]), "+f"(d[1]), "+f"(d[2]), "+f"(d[3])
        : "r"(a[0]), "r"(a[1]), "r"(a[2]), "r"(a[3]), "r"(b0), "r"(b1));
}

__device__ __forceinline__ uint32_t h2_as_u32(__half2 h) {
    uint32_t u;
    memcpy(&u, &h, 4);
    return u;
}
__device__ __forceinline__ __half2 u32_as_h2(uint32_t u) {
    __half2 h;
    memcpy(&h, &u, 4);
    return h;
}

// ----------------------------------------------------------------------------
// Kernel 0: pack W1 into fp16 m16n8k16 B-fragment order (once; 64KB, L2-hot).
// ----------------------------------------------------------------------------
__global__ void pack_w1_kernel(const float* __restrict__ W1)
{
    int i = blockIdx.x * blockDim.x + threadIdx.x;
    if (i >= 2 * 8 * 16 * 32) return;
    int o  = i >> 12;
    int kc = (i >> 9) & 7;
    int nf = (i >> 5) & 15;
    int ln = i & 31;
    int g  = ln >> 2, tq = ln & 3;
    int n  = nf * 8 + g;
    int k0 = o * 128 + kc * 16 + 2 * tq;
    __half2 b0 = __floats2half2_rn(W1[(size_t)k0 * HID + n],       W1[(size_t)(k0 + 1) * HID + n]);
    __half2 b1 = __floats2half2_rn(W1[(size_t)(k0 + 8) * HID + n], W1[(size_t)(k0 + 9) * HID + n]);
    g_W1fh[i] = make_uint2(h2_as_u32(b0), h2_as_u32(b1));
}

// ----------------------------------------------------------------------------
// Kernel 1: node projection via fp16 mma (m16n8k16); B-frags LDG'd from
// g_W1fh (L2-hot). Block tile M=128 x N=128 (one half). A streamed in
// K-chunks of 32 (fp16), double buffered. Warp tile 64x32 = 4x4 frags.
// ----------------------------------------------------------------------------
#define NP_AW 20
#define NP_SMEM_BYTES (2 * 128 * NP_AW * 4)

__global__ void __launch_bounds__(256, 3) node_proj_mma_kernel(
    const float* __restrict__ x, int n_nodes)
{
    extern __shared__ uint32_t As[];               // [2][128 m][20 w] fp16x2

    const int tid  = threadIdx.x;
    const int wid  = tid >> 5;
    const int lane = tid & 31;
    const int g    = lane >> 2;
    const int tq   = lane & 3;
    const int wm   = wid >> 2;       // 0..1
    const int wn   = wid & 3;        // 0..3

    const int bm = blockIdx.x * 128;
    const int o  = blockIdx.y;       // which W half / P half

    const int a_k4 = (tid & 7) * 4;  // k offset (halves) within 32-chunk
    const int a_rb = tid >> 3;
    auto loadA = [&](int buf, int ch) {
        uint32_t* dstp = As + buf * (128 * NP_AW);
#pragma unroll
        for (int p = 0; p < 4; p++) {
            int r = a_rb + p * 32;
            int grow = bm + r;
            float4 v = make_float4(0.f, 0.f, 0.f, 0.f);
            if (grow < n_nodes)
                v = *(const float4*)(x + (size_t)grow * HID + ch * 32 + a_k4);
            __half2 p0 = __floats2half2_rn(v.x, v.y);
            __half2 p1 = __floats2half2_rn(v.z, v.w);
            *(uint2*)(dstp + r * NP_AW + (a_k4 >> 1)) =
                make_uint2(h2_as_u32(p0), h2_as_u32(p1));
        }
    };

    loadA(0, 0);
    __syncthreads();

    float acc[4][4][4];
#pragma unroll
    for (int a = 0; a < 4; a++)
#pragma unroll
        for (int b = 0; b < 4; b++)
#pragma unroll
            for (int c = 0; c < 4; c++) acc[a][b][c] = 0.f;

    const uint2* __restrict__ wf_base = g_W1fh + ((size_t)o * 8 * 16 + wn * 4) * 32 + lane;

#pragma unroll
    for (int ch = 0; ch < 4; ch++) {
        if (ch < 3) loadA((ch + 1) & 1, ch + 1);
        const uint32_t* Ab = As + (ch & 1) * (128 * NP_AW)
                                + (wm * 64 + g) * NP_AW + tq;
#pragma unroll
        for (int kk = 0; kk < 2; kk++) {          // two k16 chunks per k32
            uint2 bfr[4];
            const uint2* wf = wf_base + (size_t)(ch * 2 + kk) * 16 * 32;
#pragma unroll
            for (int nf = 0; nf < 4; nf++) bfr[nf] = wf[nf * 32];

            uint32_t afr[4][4];
#pragma unroll
            for (int mf = 0; mf < 4; mf++) {
                const uint32_t* ap = Ab + mf * 16 * NP_AW + kk * 8;
                afr[mf][0] = ap[0];
                afr[mf][1] = ap[8 * NP_AW];
                afr[mf][2] = ap[4];
                afr[mf][3] = ap[8 * NP_AW + 4];
            }
#pragma unroll
            for (int mf = 0; mf < 4; mf++)
#pragma unroll
                for (int nf = 0; nf < 4; nf++)
                    mma_f16(acc[mf][nf], afr[mf], bfr[nf].x, bfr[nf].y);
        }
        __syncthreads();
    }

    // epilogue: fp16 P
#pragma unroll
    for (int mf = 0; mf < 4; mf++) {
        int r0g = bm + wm * 64 + mf * 16 + g;
#pragma unroll
        for (int nf = 0; nf < 4; nf++) {
            int col = o * 128 + wn * 32 + nf * 8 + 2 * tq;
            if (r0g < n_nodes)
                *(__half2*)(g_Ph + (size_t)r0g * 256 + col) =
                    __floats2half2_rn(acc[mf][nf][0], acc[mf][nf][1]);
            if (r0g + 8 < n_nodes)
                *(__half2*)(g_Ph + (size_t)(r0g + 8) * 256 + col) =
                    __floats2half2_rn(acc[mf][nf][2], acc[mf][nf][3]);
        }
    }
}

// ----------------------------------------------------------------------------
// Kernel 2: edge MLP, fp16 layer-2 mma. 8 warps/block, 16-edge tiles/warp.
// Layer-1 gather explicitly batched: 2 groups of 8 rows, all 16 LDG.64 of a
// group in flight before consumption (MLP=16). launch_bounds(256,3) gives
// ptxas ~84 regs for the load batch.
// ----------------------------------------------------------------------------
#define EWARPS 8
#define ETHREADS (EWARPS * 32)
#define HS 136                          // halves per hbuf row (68 words)
#define HBUF_WORDS (16 * (HS / 2))
#define W2F_COUNT (8 * 4 * 32)          // 1024 uint2 = 8KB
#define EDGE_SMEM_BYTES (W2F_COUNT * 8 + 256 + EWARPS * HBUF_WORDS * 4)

__global__ void __launch_bounds__(ETHREADS, 3) edge_mlp_kernel(
    const int*   __restrict__ edge_index,   // [2*E]: src then dst
    const float* __restrict__ eattr,        // [E]
    const float* __restrict__ W1,           // [257*128], row 256 = w1c
    const float* __restrict__ b1,           // [128]
    const float* __restrict__ W2,           // [128*32]
    const float* __restrict__ b2,           // [32]
    const float* __restrict__ W3,           // [32]
    const float* __restrict__ b3,           // [1]
    float*       __restrict__ out,          // [E]
    int n_edges)
{
    extern __shared__ char smem[];
    uint2* __restrict__ w2f  = (uint2*)smem;                       // fp16 B frags
    float* __restrict__ s_b2 = (float*)(smem + W2F_COUNT * 8);     // [32]
    float* __restrict__ s_w3 = s_b2 + 32;                          // [32]
    uint32_t* __restrict__ hb_all = (uint32_t*)(smem + W2F_COUNT * 8 + 256);

    const int tid  = threadIdx.x;
    const int wid  = tid >> 5;
    const int lane = tid & 31;
    const int g    = lane >> 2;
    const int tq   = lane & 3;
    uint32_t* __restrict__ hbuf = hb_all + wid * HBUF_WORDS;

    // --- pack W2 into fp16 m16n8k16 B-fragment order ---
    for (int i = tid; i < W2F_COUNT; i += ETHREADS) {
        int kc = i >> 7;
        int nt = (i >> 5) & 3;
        int ln = i & 31;
        int col = nt * 8 + (ln >> 2);
        int k0  = kc * 16 + (ln & 3) * 2;
        __half2 lo = __floats2half2_rn(W2[k0 * 32 + col],       W2[(k0 + 1) * 32 + col]);
        __half2 hi = __floats2half2_rn(W2[(k0 + 8) * 32 + col], W2[(k0 + 9) * 32 + col]);
        w2f[i] = make_uint2(h2_as_u32(lo), h2_as_u32(hi));
    }
    if (tid < 32) { s_b2[tid] = b2[tid]; s_w3[tid] = W3[tid]; }
    __syncthreads();

    // --- per-lane layer-1 constants as half2 (lane covers h cols 4l..4l+3) ---
    const float4 wcf = ((const float4*)(W1 + 256 * HID))[lane];
    const float4 b1f = ((const float4*)b1)[lane];
    const __half2 wc0 = __floats2half2_rn(wcf.x, wcf.y);
    const __half2 wc1 = __floats2half2_rn(wcf.z, wcf.w);
    const __half2 bb0 = __floats2half2_rn(b1f.x, b1f.y);
    const __half2 bb1v = __floats2half2_rn(b1f.z, b1f.w);
    const __half2 zero2 = __floats2half2_rn(0.f, 0.f);
    const float  b3v = b3[0];

    const int* __restrict__ src = edge_index;
    const int* __restrict__ dst = edge_index + n_edges;

    const int gw = blockIdx.x * EWARPS + wid;
    const int nwarps = gridDim.x * EWARPS;
    const int ntiles = (n_edges + 15) >> 4;

    for (int t = gw; t < ntiles; t += nwarps) {
        const int base = t << 4;

        // ---- stage edge data (lanes 0..15), broadcast via shfl ----
        int sA = 0, dA = 0;
        float eaA = 0.f;
        if (lane < 16) {
            int e = base + lane;
            if (e < n_edges) { sA = src[e]; dA = dst[e]; eaA = eattr[e]; }
        }

        // ---- layer 1: batched gather (2 groups x 8 rows, 16 LDG.64 in flight)
#pragma unroll
        for (int bb = 0; bb < 2; bb++) {
            uint2 ua[8], ub[8];
            float ea8[8];
#pragma unroll
            for (int r = 0; r < 8; r++) {
                int rr = bb * 8 + r;
                int s  = __shfl_sync(0xffffffffu, sA, rr);
                int dd = __shfl_sync(0xffffffffu, dA, rr);
                ea8[r] = __shfl_sync(0xffffffffu, eaA, rr);
                ua[r] = *((const uint2*)(g_Ph + (size_t)s  * 256) + lane);
                ub[r] = *((const uint2*)(g_Ph + (size_t)dd * 256 + 128) + lane);
            }
#pragma unroll
            for (int r = 0; r < 8; r++) {
                int rr = bb * 8 + r;
                __half2 ea2 = __float2half2_rn(ea8[r]);
                __half2 h0 = __hadd2(__hadd2(u32_as_h2(ua[r].x), u32_as_h2(ub[r].x)), bb0);
                __half2 h1 = __hadd2(__hadd2(u32_as_h2(ua[r].y), u32_as_h2(ub[r].y)), bb1v);
                h0 = __hmax2(__hfma2(ea2, wc0, h0), zero2);
                h1 = __hmax2(__hfma2(ea2, wc1, h1), zero2);
                *((uint2*)(hbuf + rr * (HS / 2)) + lane) =
                    make_uint2(h2_as_u32(h0), h2_as_u32(h1));
            }
        }
        __syncwarp();

        // ---- layer 2: fp16 mma, D[16][32], 8 k-chunks of 16 ----
        float dacc[4][4];
#pragma unroll
        for (int nt = 0; nt < 4; nt++)
#pragma unroll
            for (int j = 0; j < 4; j++) dacc[nt][j] = 0.f;

#pragma unroll
        for (int kc = 0; kc < 8; kc++) {
            const uint32_t* ap = hbuf + g * (HS / 2) + kc * 8 + tq;
            uint32_t a[4];
            a[0] = ap[0];
            a[1] = ap[8 * (HS / 2)];
            a[2] = ap[4];
            a[3] = ap[8 * (HS / 2) + 4];
            const uint2* wrow = w2f + kc * 128 + lane;
#pragma unroll
            for (int nt = 0; nt < 4; nt++) {
                uint2 bv = wrow[nt * 32];
                mma_f16(dacc[nt], a, bv.x, bv.y);
            }
        }
        __syncwarp();   // hbuf safe before next tile overwrites

        // ---- layer 3: +b2, relu, *W3, quad-reduce, sigmoid ----
        float acc0 = 0.f, acc1 = 0.f;   // rows base+g and base+g+8
#pragma unroll
        for (int nt = 0; nt < 4; nt++) {
#pragma unroll
            for (int i = 0; i < 2; i++) {
                int col = nt * 8 + 2 * tq + i;
                float w3c = s_w3[col], b2c = s_b2[col];
                acc0 = fmaf(fmaxf(dacc[nt][i]     + b2c, 0.f), w3c, acc0);
                acc1 = fmaf(fmaxf(dacc[nt][2 + i] + b2c, 0.f), w3c, acc1);
            }
        }
        acc0 += __shfl_xor_sync(0xffffffffu, acc0, 1);
        acc0 += __shfl_xor_sync(0xffffffffu, acc0, 2);
        acc1 += __shfl_xor_sync(0xffffffffu, acc1, 1);
        acc1 += __shfl_xor_sync(0xffffffffu, acc1, 2);
        if (tq == 0) {
            int e0 = base + g;
            int e1 = base + g + 8;
            if (e0 < n_edges) {
                float z = acc0 + b3v;
                out[e0] = 1.f / (1.f + __expf(-z));
            }
            if (e1 < n_edges) {
                float z = acc1 + b3v;
                out[e1] = 1.f / (1.f + __expf(-z));
            }
        }
    }
}

// ----------------------------------------------------------------------------
// Launch
// ----------------------------------------------------------------------------
extern "C" void kernel_launch(void* const* d_in, const int* in_sizes, int n_in,
                              void* d_out, int out_size)
{
    const float* x  = (const float*)d_in[0];
    const int*   ei = (const int*)d_in[1];
    const float* ea = (const float*)d_in[2];
    const float* W1 = (const float*)d_in[3];
    const float* b1 = (const float*)d_in[4];
    const float* W2 = (const float*)d_in[5];
    const float* b2 = (const float*)d_in[6];
    const float* W3 = (const float*)d_in[7];
    const float* b3 = (const float*)d_in[8];
    float*       out = (float*)d_out;

    const int n_nodes = in_sizes[0] / HID;     // 100000
    const int n_edges = in_sizes[2];           // 1000000

    static int smem_set = 0;
    if (!smem_set) {
        cudaFuncSetAttribute(node_proj_mma_kernel,
                             cudaFuncAttributeMaxDynamicSharedMemorySize, NP_SMEM_BYTES);
        cudaFuncSetAttribute(edge_mlp_kernel,
                             cudaFuncAttributeMaxDynamicSharedMemorySize, EDGE_SMEM_BYTES);
        smem_set = 1;
    }

    // Kernel 0: pack W1 fragments (L2-hot afterwards)
    pack_w1_kernel<<<32, 256>>>(W1);

    // Kernel 1: node projections (fp16 mma, fp16 output)
    dim3 g1((n_nodes + 127) / 128, 2);
    node_proj_mma_kernel<<<g1, 256, NP_SMEM_BYTES>>>(x, n_nodes);

    // Kernel 2: edge MLP (batched gather, fp16 mma layer-2)
    const int blocks = 592;
    edge_mlp_kernel<<<blocks, ETHREADS, EDGE_SMEM_BYTES>>>(
        ei, ea, W1, b1, W2, b2, W3, b3, out, n_edges);
}

// round 11
// speedup vs baseline: 1.0305x; 1.0305x over previous
#include <cuda_runtime.h>
#include <cuda_fp16.h>
#include <cstdint>

#define HID 128
#define NNODES 100000

// Node projections, fp16: P[node][0:128] = x@W1[0:128], [128:256] = x@W1[128:256]
__device__ __half g_Ph[(size_t)NNODES * 256];
// W1 packed into fp16 m16n8k16 B-fragment order: [2 halves][8 kc][16 nf][32 lanes] uint2
__device__ uint2 g_W1fh[2 * 8 * 16 * 32];

// ----------------------------------------------------------------------------
// mma helper (portable: sm_103 PTX target has no tcgen05)
// fp16: D[16x8] += A[16x16] * B[16x8], fp32 accum
// ----------------------------------------------------------------------------
__device__ __forceinline__ void mma_f16(float* d, const uint32_t* a, uint32_t b0, uint32_t b1) {
    asm volatile(
        "mma.sync.aligned.m16n8k16.row.col.f32.f16.f16.f32 "
        "{%0,%1,%2,%3}, {%4,%5,%6,%7}, {%8,%9}, {%0,%1,%2,%3};"
        : "+f"(d[0]), "+f"(d[1]), "+f"(d[2]), "+f"(d[3])
        : "r"(a[0]), "r"(a[1]), "r"(a[2]), "r"(a[3]), "r"(b0), "r"(b1));
}

__device__ __forceinline__ uint32_t h2_as_u32(__half2 h) {
    uint32_t u;
    memcpy(&u, &h, 4);
    return u;
}
__device__ __forceinline__ __half2 u32_as_h2(uint32_t u) {
    __half2 h;
    memcpy(&h, &u, 4);
    return h;
}

// ----------------------------------------------------------------------------
// Kernel 0: pack W1 into fp16 m16n8k16 B-fragment order (once; 64KB, L2-hot).
// ----------------------------------------------------------------------------
__global__ void pack_w1_kernel(const float* __restrict__ W1)
{
    int i = blockIdx.x * blockDim.x + threadIdx.x;
    if (i >= 2 * 8 * 16 * 32) return;
    int o  = i >> 12;
    int kc = (i >> 9) & 7;
    int nf = (i >> 5) & 15;
    int ln = i & 31;
    int g  = ln >> 2, tq = ln & 3;
    int n  = nf * 8 + g;
    int k0 = o * 128 + kc * 16 + 2 * tq;
    __half2 b0 = __floats2half2_rn(W1[(size_t)k0 * HID + n],       W1[(size_t)(k0 + 1) * HID + n]);
    __half2 b1 = __floats2half2_rn(W1[(size_t)(k0 + 8) * HID + n], W1[(size_t)(k0 + 9) * HID + n]);
    g_W1fh[i] = make_uint2(h2_as_u32(b0), h2_as_u32(b1));
}

// ----------------------------------------------------------------------------
// Kernel 1: node projection via fp16 mma (m16n8k16); B-frags LDG'd from
// g_W1fh (L2-hot). Block tile M=128 x N=128 (one half). A streamed in
// K-chunks of 32 (fp16), double buffered. Warp tile 64x32 = 4x4 frags.
// ----------------------------------------------------------------------------
#define NP_AW 20
#define NP_SMEM_BYTES (2 * 128 * NP_AW * 4)

__global__ void __launch_bounds__(256, 3) node_proj_mma_kernel(
    const float* __restrict__ x, int n_nodes)
{
    extern __shared__ uint32_t As[];               // [2][128 m][20 w] fp16x2

    const int tid  = threadIdx.x;
    const int wid  = tid >> 5;
    const int lane = tid & 31;
    const int g    = lane >> 2;
    const int tq   = lane & 3;
    const int wm   = wid >> 2;       // 0..1
    const int wn   = wid & 3;        // 0..3

    const int bm = blockIdx.x * 128;
    const int o  = blockIdx.y;       // which W half / P half

    const int a_k4 = (tid & 7) * 4;  // k offset (halves) within 32-chunk
    const int a_rb = tid >> 3;
    auto loadA = [&](int buf, int ch) {
        uint32_t* dstp = As + buf * (128 * NP_AW);
#pragma unroll
        for (int p = 0; p < 4; p++) {
            int r = a_rb + p * 32;
            int grow = bm + r;
            float4 v = make_float4(0.f, 0.f, 0.f, 0.f);
            if (grow < n_nodes)
                v = *(const float4*)(x + (size_t)grow * HID + ch * 32 + a_k4);
            __half2 p0 = __floats2half2_rn(v.x, v.y);
            __half2 p1 = __floats2half2_rn(v.z, v.w);
            *(uint2*)(dstp + r * NP_AW + (a_k4 >> 1)) =
                make_uint2(h2_as_u32(p0), h2_as_u32(p1));
        }
    };

    loadA(0, 0);
    __syncthreads();

    float acc[4][4][4];
#pragma unroll
    for (int a = 0; a < 4; a++)
#pragma unroll
        for (int b = 0; b < 4; b++)
#pragma unroll
            for (int c = 0; c < 4; c++) acc[a][b][c] = 0.f;

    const uint2* __restrict__ wf_base = g_W1fh + ((size_t)o * 8 * 16 + wn * 4) * 32 + lane;

#pragma unroll
    for (int ch = 0; ch < 4; ch++) {
        if (ch < 3) loadA((ch + 1) & 1, ch + 1);
        const uint32_t* Ab = As + (ch & 1) * (128 * NP_AW)
                                + (wm * 64 + g) * NP_AW + tq;
#pragma unroll
        for (int kk = 0; kk < 2; kk++) {          // two k16 chunks per k32
            uint2 bfr[4];
            const uint2* wf = wf_base + (size_t)(ch * 2 + kk) * 16 * 32;
#pragma unroll
            for (int nf = 0; nf < 4; nf++) bfr[nf] = wf[nf * 32];

            uint32_t afr[4][4];
#pragma unroll
            for (int mf = 0; mf < 4; mf++) {
                const uint32_t* ap = Ab + mf * 16 * NP_AW + kk * 8;
                afr[mf][0] = ap[0];
                afr[mf][1] = ap[8 * NP_AW];
                afr[mf][2] = ap[4];
                afr[mf][3] = ap[8 * NP_AW + 4];
            }
#pragma unroll
            for (int mf = 0; mf < 4; mf++)
#pragma unroll
                for (int nf = 0; nf < 4; nf++)
                    mma_f16(acc[mf][nf], afr[mf], bfr[nf].x, bfr[nf].y);
        }
        __syncthreads();
    }

    // epilogue: fp16 P
#pragma unroll
    for (int mf = 0; mf < 4; mf++) {
        int r0g = bm + wm * 64 + mf * 16 + g;
#pragma unroll
        for (int nf = 0; nf < 4; nf++) {
            int col = o * 128 + wn * 32 + nf * 8 + 2 * tq;
            if (r0g < n_nodes)
                *(__half2*)(g_Ph + (size_t)r0g * 256 + col) =
                    __floats2half2_rn(acc[mf][nf][0], acc[mf][nf][1]);
            if (r0g + 8 < n_nodes)
                *(__half2*)(g_Ph + (size_t)(r0g + 8) * 256 + col) =
                    __floats2half2_rn(acc[mf][nf][2], acc[mf][nf][3]);
        }
    }
}

// ----------------------------------------------------------------------------
// Kernel 2: edge MLP, fp16 layer-2 mma. 4 warps/block (128 thr), each warp
// owns independent 32-edge tiles (two m16 subtiles) so every W2 B-fragment
// LDS is shared across 2 MMAs -> w2f smem traffic per edge halves.
// launch_bounds(128,5): 5 blocks/SM, 20 warps/SM, ~102 regs available.
// ----------------------------------------------------------------------------
#define EWARPS 4
#define ETHREADS (EWARPS * 32)
#define ETILE 32                        // edges per warp-tile
#define HS 136                          // halves per hbuf row (68 words)
#define HBUF_WORDS (ETILE * (HS / 2))   // 32 rows
#define W2F_COUNT (8 * 4 * 32)          // 1024 uint2 = 8KB
#define EDGE_SMEM_BYTES (W2F_COUNT * 8 + 256 + EWARPS * HBUF_WORDS * 4)

__global__ void __launch_bounds__(ETHREADS, 5) edge_mlp_kernel(
    const int*   __restrict__ edge_index,   // [2*E]: src then dst
    const float* __restrict__ eattr,        // [E]
    const float* __restrict__ W1,           // [257*128], row 256 = w1c
    const float* __restrict__ b1,           // [128]
    const float* __restrict__ W2,           // [128*32]
    const float* __restrict__ b2,           // [32]
    const float* __restrict__ W3,           // [32]
    const float* __restrict__ b3,           // [1]
    float*       __restrict__ out,          // [E]
    int n_edges)
{
    extern __shared__ char smem[];
    uint2* __restrict__ w2f  = (uint2*)smem;                       // fp16 B frags
    float* __restrict__ s_b2 = (float*)(smem + W2F_COUNT * 8);     // [32]
    float* __restrict__ s_w3 = s_b2 + 32;                          // [32]
    uint32_t* __restrict__ hb_all = (uint32_t*)(smem + W2F_COUNT * 8 + 256);

    const int tid  = threadIdx.x;
    const int wid  = tid >> 5;
    const int lane = tid & 31;
    const int g    = lane >> 2;
    const int tq   = lane & 3;
    uint32_t* __restrict__ hbuf = hb_all + wid * HBUF_WORDS;

    // --- pack W2 into fp16 m16n8k16 B-fragment order ---
    for (int i = tid; i < W2F_COUNT; i += ETHREADS) {
        int kc = i >> 7;
        int nt = (i >> 5) & 3;
        int ln = i & 31;
        int col = nt * 8 + (ln >> 2);
        int k0  = kc * 16 + (ln & 3) * 2;
        __half2 lo = __floats2half2_rn(W2[k0 * 32 + col],       W2[(k0 + 1) * 32 + col]);
        __half2 hi = __floats2half2_rn(W2[(k0 + 8) * 32 + col], W2[(k0 + 9) * 32 + col]);
        w2f[i] = make_uint2(h2_as_u32(lo), h2_as_u32(hi));
    }
    if (tid < 32) { s_b2[tid] = b2[tid]; s_w3[tid] = W3[tid]; }
    __syncthreads();

    // --- per-lane layer-1 constants as half2 (lane covers h cols 4l..4l+3) ---
    const float4 wcf = ((const float4*)(W1 + 256 * HID))[lane];
    const float4 b1f = ((const float4*)b1)[lane];
    const __half2 wc0 = __floats2half2_rn(wcf.x, wcf.y);
    const __half2 wc1 = __floats2half2_rn(wcf.z, wcf.w);
    const __half2 bb0 = __floats2half2_rn(b1f.x, b1f.y);
    const __half2 bb1v = __floats2half2_rn(b1f.z, b1f.w);
    const __half2 zero2 = __floats2half2_rn(0.f, 0.f);
    const float  b3v = b3[0];

    const int* __restrict__ src = edge_index;
    const int* __restrict__ dst = edge_index + n_edges;

    const int gw = blockIdx.x * EWARPS + wid;
    const int nwarps = gridDim.x * EWARPS;
    const int ntiles = (n_edges + ETILE - 1) / ETILE;

    for (int t = gw; t < ntiles; t += nwarps) {
        const int base = t * ETILE;

        // ---- stage edge data: every lane owns one of the 32 edges ----
        int sA = 0, dA = 0;
        float eaA = 0.f;
        {
            int e = base + lane;
            if (e < n_edges) { sA = src[e]; dA = dst[e]; eaA = eattr[e]; }
        }

        // ---- layer 1: gather + relu -> fp16 smem tile [32][HS] ----
#pragma unroll
        for (int rr = 0; rr < ETILE; rr++) {
            int   s  = __shfl_sync(0xffffffffu, sA, rr);
            int   dd = __shfl_sync(0xffffffffu, dA, rr);
            float ea = __shfl_sync(0xffffffffu, eaA, rr);
            __half2 ea2 = __float2half2_rn(ea);
            uint2 ua = *((const uint2*)(g_Ph + (size_t)s  * 256) + lane);
            uint2 ub = *((const uint2*)(g_Ph + (size_t)dd * 256 + 128) + lane);
            __half2 h0 = __hadd2(__hadd2(u32_as_h2(ua.x), u32_as_h2(ub.x)), bb0);
            __half2 h1 = __hadd2(__hadd2(u32_as_h2(ua.y), u32_as_h2(ub.y)), bb1v);
            h0 = __hmax2(__hfma2(ea2, wc0, h0), zero2);
            h1 = __hmax2(__hfma2(ea2, wc1, h1), zero2);
            *((uint2*)(hbuf + rr * (HS / 2)) + lane) =
                make_uint2(h2_as_u32(h0), h2_as_u32(h1));
        }
        __syncwarp();

        // ---- layer 2: fp16 mma, D[32][32]; B-frags shared across 2 subtiles
        float dacc[2][4][4];
#pragma unroll
        for (int tt = 0; tt < 2; tt++)
#pragma unroll
            for (int nt = 0; nt < 4; nt++)
#pragma unroll
                for (int j = 0; j < 4; j++) dacc[tt][nt][j] = 0.f;

#pragma unroll
        for (int kc = 0; kc < 8; kc++) {
            uint2 bv[4];
            const uint2* wrow = w2f + kc * 128 + lane;
#pragma unroll
            for (int nt = 0; nt < 4; nt++) bv[nt] = wrow[nt * 32];
#pragma unroll
            for (int tt = 0; tt < 2; tt++) {
                const uint32_t* ap = hbuf + (tt * 16 + g) * (HS / 2) + kc * 8 + tq;
                uint32_t a[4];
                a[0] = ap[0];
                a[1] = ap[8 * (HS / 2)];
                a[2] = ap[4];
                a[3] = ap[8 * (HS / 2) + 4];
#pragma unroll
                for (int nt = 0; nt < 4; nt++)
                    mma_f16(dacc[tt][nt], a, bv[nt].x, bv[nt].y);
            }
        }
        __syncwarp();   // hbuf safe before next tile overwrites

        // ---- layer 3: +b2, relu, *W3, quad-reduce, sigmoid ----
#pragma unroll
        for (int tt = 0; tt < 2; tt++) {
            float acc0 = 0.f, acc1 = 0.f;   // rows base+16tt+g and +8
#pragma unroll
            for (int nt = 0; nt < 4; nt++) {
#pragma unroll
                for (int i = 0; i < 2; i++) {
                    int col = nt * 8 + 2 * tq + i;
                    float w3c = s_w3[col], b2c = s_b2[col];
                    acc0 = fmaf(fmaxf(dacc[tt][nt][i]     + b2c, 0.f), w3c, acc0);
                    acc1 = fmaf(fmaxf(dacc[tt][nt][2 + i] + b2c, 0.f), w3c, acc1);
                }
            }
            acc0 += __shfl_xor_sync(0xffffffffu, acc0, 1);
            acc0 += __shfl_xor_sync(0xffffffffu, acc0, 2);
            acc1 += __shfl_xor_sync(0xffffffffu, acc1, 1);
            acc1 += __shfl_xor_sync(0xffffffffu, acc1, 2);
            if (tq == 0) {
                int e0 = base + tt * 16 + g;
                int e1 = e0 + 8;
                if (e0 < n_edges) {
                    float z = acc0 + b3v;
                    out[e0] = 1.f / (1.f + __expf(-z));
                }
                if (e1 < n_edges) {
                    float z = acc1 + b3v;
                    out[e1] = 1.f / (1.f + __expf(-z));
                }
            }
        }
    }
}

// ----------------------------------------------------------------------------
// Launch
// ----------------------------------------------------------------------------
extern "C" void kernel_launch(void* const* d_in, const int* in_sizes, int n_in,
                              void* d_out, int out_size)
{
    const float* x  = (const float*)d_in[0];
    const int*   ei = (const int*)d_in[1];
    const float* ea = (const float*)d_in[2];
    const float* W1 = (const float*)d_in[3];
    const float* b1 = (const float*)d_in[4];
    const float* W2 = (const float*)d_in[5];
    const float* b2 = (const float*)d_in[6];
    const float* W3 = (const float*)d_in[7];
    const float* b3 = (const float*)d_in[8];
    float*       out = (float*)d_out;

    const int n_nodes = in_sizes[0] / HID;     // 100000
    const int n_edges = in_sizes[2];           // 1000000

    static int smem_set = 0;
    if (!smem_set) {
        cudaFuncSetAttribute(node_proj_mma_kernel,
                             cudaFuncAttributeMaxDynamicSharedMemorySize, NP_SMEM_BYTES);
        cudaFuncSetAttribute(edge_mlp_kernel,
                             cudaFuncAttributeMaxDynamicSharedMemorySize, EDGE_SMEM_BYTES);
        smem_set = 1;
    }

    // Kernel 0: pack W1 fragments (L2-hot afterwards)
    pack_w1_kernel<<<32, 256>>>(W1);

    // Kernel 1: node projections (fp16 mma, fp16 output)
    dim3 g1((n_nodes + 127) / 128, 2);
    node_proj_mma_kernel<<<g1, 256, NP_SMEM_BYTES>>>(x, n_nodes);

    // Kernel 2: edge MLP (32-edge warp tiles, shared B-frags)
    const int blocks = 740;   // 5 blocks/SM
    edge_mlp_kernel<<<blocks, ETHREADS, EDGE_SMEM_BYTES>>>(
        ei, ea, W1, b1, W2, b2, W3, b3, out, n_edges);
}

// round 12
// speedup vs baseline: 1.0721x; 1.0403x over previous
#include <cuda_runtime.h>
#include <cuda_fp16.h>
#include <cstdint>

#define HID 128
#define NNODES 100000

// Node projections, fp16: P[node][0:128] = x@W1[0:128], [128:256] = x@W1[128:256]
__device__ __half g_Ph[(size_t)NNODES * 256];
// W1 packed into fp16 m16n8k16 B-fragment order: [2 halves][8 kc][16 nf][32 lanes] uint2
__device__ uint2 g_W1fh[2 * 8 * 16 * 32];

// ----------------------------------------------------------------------------
// mma helpers (portable: sm_103 PTX target has no tcgen05)
// ----------------------------------------------------------------------------
__device__ __forceinline__ void mma_f16(float* d, const uint32_t* a, uint32_t b0, uint32_t b1) {
    asm volatile(
        "mma.sync.aligned.m16n8k16.row.col.f32.f16.f16.f32 "
        "{%0,%1,%2,%3}, {%4,%5,%6,%7}, {%8,%9}, {%0,%1,%2,%3};"
        : "+f"(d[0]), "+f"(d[1]), "+f"(d[2]), "+f"(d[3])
        : "r"(a[0]), "r"(a[1]), "r"(a[2]), "r"(a[3]), "r"(b0), "r"(b1));
}

__device__ __forceinline__ void ldmatrix_x4(uint32_t* r, uint32_t smem_addr) {
    asm volatile(
        "ldmatrix.sync.aligned.m8n8.x4.shared.b16 {%0,%1,%2,%3}, [%4];"
        : "=r"(r[0]), "=r"(r[1]), "=r"(r[2]), "=r"(r[3])
        : "r"(smem_addr));
}

__device__ __forceinline__ uint32_t h2_as_u32(__half2 h) {
    uint32_t u;
    memcpy(&u, &h, 4);
    return u;
}
__device__ __forceinline__ __half2 u32_as_h2(uint32_t u) {
    __half2 h;
    memcpy(&h, &u, 4);
    return h;
}

// ----------------------------------------------------------------------------
// Kernel 0: pack W1 into fp16 m16n8k16 B-fragment order (once; 64KB, L2-hot).
// ----------------------------------------------------------------------------
__global__ void pack_w1_kernel(const float* __restrict__ W1)
{
    int i = blockIdx.x * blockDim.x + threadIdx.x;
    if (i >= 2 * 8 * 16 * 32) return;
    int o  = i >> 12;
    int kc = (i >> 9) & 7;
    int nf = (i >> 5) & 15;
    int ln = i & 31;
    int g  = ln >> 2, tq = ln & 3;
    int n  = nf * 8 + g;
    int k0 = o * 128 + kc * 16 + 2 * tq;
    __half2 b0 = __floats2half2_rn(W1[(size_t)k0 * HID + n],       W1[(size_t)(k0 + 1) * HID + n]);
    __half2 b1 = __floats2half2_rn(W1[(size_t)(k0 + 8) * HID + n], W1[(size_t)(k0 + 9) * HID + n]);
    g_W1fh[i] = make_uint2(h2_as_u32(b0), h2_as_u32(b1));
}

// ----------------------------------------------------------------------------
// Kernel 1: node projection via fp16 mma (m16n8k16); B-frags LDG'd from
// g_W1fh (L2-hot). Block tile M=128 x N=128 (one half). A streamed in
// K-chunks of 32 (fp16), double buffered. Warp tile 64x32 = 4x4 frags.
// ----------------------------------------------------------------------------
#define NP_AW 20
#define NP_SMEM_BYTES (2 * 128 * NP_AW * 4)

__global__ void __launch_bounds__(256, 3) node_proj_mma_kernel(
    const float* __restrict__ x, int n_nodes)
{
    extern __shared__ uint32_t As[];               // [2][128 m][20 w] fp16x2

    const int tid  = threadIdx.x;
    const int wid  = tid >> 5;
    const int lane = tid & 31;
    const int g    = lane >> 2;
    const int tq   = lane & 3;
    const int wm   = wid >> 2;       // 0..1
    const int wn   = wid & 3;        // 0..3

    const int bm = blockIdx.x * 128;
    const int o  = blockIdx.y;       // which W half / P half

    const int a_k4 = (tid & 7) * 4;  // k offset (halves) within 32-chunk
    const int a_rb = tid >> 3;
    auto loadA = [&](int buf, int ch) {
        uint32_t* dstp = As + buf * (128 * NP_AW);
#pragma unroll
        for (int p = 0; p < 4; p++) {
            int r = a_rb + p * 32;
            int grow = bm + r;
            float4 v = make_float4(0.f, 0.f, 0.f, 0.f);
            if (grow < n_nodes)
                v = *(const float4*)(x + (size_t)grow * HID + ch * 32 + a_k4);
            __half2 p0 = __floats2half2_rn(v.x, v.y);
            __half2 p1 = __floats2half2_rn(v.z, v.w);
            *(uint2*)(dstp + r * NP_AW + (a_k4 >> 1)) =
                make_uint2(h2_as_u32(p0), h2_as_u32(p1));
        }
    };

    loadA(0, 0);
    __syncthreads();

    float acc[4][4][4];
#pragma unroll
    for (int a = 0; a < 4; a++)
#pragma unroll
        for (int b = 0; b < 4; b++)
#pragma unroll
            for (int c = 0; c < 4; c++) acc[a][b][c] = 0.f;

    const uint2* __restrict__ wf_base = g_W1fh + ((size_t)o * 8 * 16 + wn * 4) * 32 + lane;

#pragma unroll
    for (int ch = 0; ch < 4; ch++) {
        if (ch < 3) loadA((ch + 1) & 1, ch + 1);
        const uint32_t* Ab = As + (ch & 1) * (128 * NP_AW)
                                + (wm * 64 + g) * NP_AW + tq;
#pragma unroll
        for (int kk = 0; kk < 2; kk++) {          // two k16 chunks per k32
            uint2 bfr[4];
            const uint2* wf = wf_base + (size_t)(ch * 2 + kk) * 16 * 32;
#pragma unroll
            for (int nf = 0; nf < 4; nf++) bfr[nf] = wf[nf * 32];

            uint32_t afr[4][4];
#pragma unroll
            for (int mf = 0; mf < 4; mf++) {
                const uint32_t* ap = Ab + mf * 16 * NP_AW + kk * 8;
                afr[mf][0] = ap[0];
                afr[mf][1] = ap[8 * NP_AW];
                afr[mf][2] = ap[4];
                afr[mf][3] = ap[8 * NP_AW + 4];
            }
#pragma unroll
            for (int mf = 0; mf < 4; mf++)
#pragma unroll
                for (int nf = 0; nf < 4; nf++)
                    mma_f16(acc[mf][nf], afr[mf], bfr[nf].x, bfr[nf].y);
        }
        __syncthreads();
    }

    // epilogue: fp16 P
#pragma unroll
    for (int mf = 0; mf < 4; mf++) {
        int r0g = bm + wm * 64 + mf * 16 + g;
#pragma unroll
        for (int nf = 0; nf < 4; nf++) {
            int col = o * 128 + wn * 32 + nf * 8 + 2 * tq;
            if (r0g < n_nodes)
                *(__half2*)(g_Ph + (size_t)r0g * 256 + col) =
                    __floats2half2_rn(acc[mf][nf][0], acc[mf][nf][1]);
            if (r0g + 8 < n_nodes)
                *(__half2*)(g_Ph + (size_t)(r0g + 8) * 256 + col) =
                    __floats2half2_rn(acc[mf][nf][2], acc[mf][nf][3]);
        }
    }
}

// ----------------------------------------------------------------------------
// Kernel 2: edge MLP, fp16 layer-2 mma. 8 warps/block, 16-edge tiles/warp
// (R9 config). Gather uses LDG.128 with 2 edges/iteration (lanes 0-15 edge
// 2i, lanes 16-31 edge 2i+1); A-fragments loaded via ldmatrix.x4.
// ----------------------------------------------------------------------------
#define EWARPS 8
#define ETHREADS (EWARPS * 32)
#define HS 136                          // halves per hbuf row (68 words)
#define HBUF_WORDS (16 * (HS / 2))
#define W2F_COUNT (8 * 4 * 32)          // 1024 uint2 = 8KB
#define EDGE_SMEM_BYTES (W2F_COUNT * 8 + 256 + EWARPS * HBUF_WORDS * 4)

__global__ void __launch_bounds__(ETHREADS, 4) edge_mlp_kernel(
    const int*   __restrict__ edge_index,   // [2*E]: src then dst
    const float* __restrict__ eattr,        // [E]
    const float* __restrict__ W1,           // [257*128], row 256 = w1c
    const float* __restrict__ b1,           // [128]
    const float* __restrict__ W2,           // [128*32]
    const float* __restrict__ b2,           // [32]
    const float* __restrict__ W3,           // [32]
    const float* __restrict__ b3,           // [1]
    float*       __restrict__ out,          // [E]
    int n_edges)
{
    extern __shared__ char smem[];
    uint2* __restrict__ w2f  = (uint2*)smem;                       // fp16 B frags
    float* __restrict__ s_b2 = (float*)(smem + W2F_COUNT * 8);     // [32]
    float* __restrict__ s_w3 = s_b2 + 32;                          // [32]
    uint32_t* __restrict__ hb_all = (uint32_t*)(smem + W2F_COUNT * 8 + 256);

    const int tid  = threadIdx.x;
    const int wid  = tid >> 5;
    const int lane = tid & 31;
    const int g    = lane >> 2;
    const int tq   = lane & 3;
    const int hl   = lane >> 4;          // half-warp: which of 2 edges per iter
    const int l16  = lane & 15;
    uint32_t* __restrict__ hbuf = hb_all + wid * HBUF_WORDS;

    // --- pack W2 into fp16 m16n8k16 B-fragment order ---
    for (int i = tid; i < W2F_COUNT; i += ETHREADS) {
        int kc = i >> 7;
        int nt = (i >> 5) & 3;
        int ln = i & 31;
        int col = nt * 8 + (ln >> 2);
        int k0  = kc * 16 + (ln & 3) * 2;
        __half2 lo = __floats2half2_rn(W2[k0 * 32 + col],       W2[(k0 + 1) * 32 + col]);
        __half2 hi = __floats2half2_rn(W2[(k0 + 8) * 32 + col], W2[(k0 + 9) * 32 + col]);
        w2f[i] = make_uint2(h2_as_u32(lo), h2_as_u32(hi));
    }
    if (tid < 32) { s_b2[tid] = b2[tid]; s_w3[tid] = W3[tid]; }
    __syncthreads();

    // --- per-lane layer-1 constants: this lane handles h cols c8..c8+7 ---
    const int c8 = l16 * 8;
    __half2 wc[4], bb[4];
    {
        const float* wrow = W1 + 256 * HID + c8;
#pragma unroll
        for (int j = 0; j < 4; j++) {
            wc[j] = __floats2half2_rn(wrow[2 * j], wrow[2 * j + 1]);
            bb[j] = __floats2half2_rn(b1[c8 + 2 * j], b1[c8 + 2 * j + 1]);
        }
    }
    const __half2 zero2 = __floats2half2_rn(0.f, 0.f);
    const float  b3v = b3[0];

    // ldmatrix base address (A-frag): row = lane&15, k-offset = (lane>>4)*8 halves
    const uint32_t hb_smem = (uint32_t)__cvta_generic_to_shared(hbuf);
    const uint32_t lm_base = hb_smem + (uint32_t)l16 * (HS / 2) * 4 + (uint32_t)hl * 16;

    const int* __restrict__ src = edge_index;
    const int* __restrict__ dst = edge_index + n_edges;

    const int gw = blockIdx.x * EWARPS + wid;
    const int nwarps = gridDim.x * EWARPS;
    const int ntiles = (n_edges + 15) >> 4;

    for (int t = gw; t < ntiles; t += nwarps) {
        const int base = t << 4;

        // ---- stage edge data (lanes 0..15), broadcast via shfl ----
        int sA = 0, dA = 0;
        float eaA = 0.f;
        if (lane < 16) {
            int e = base + lane;
            if (e < n_edges) { sA = src[e]; dA = dst[e]; eaA = eattr[e]; }
        }

        // ---- layer 1: LDG.128 gather, 2 edges per iteration ----
#pragma unroll
        for (int it = 0; it < 8; it++) {
            const int rr = 2 * it + hl;
            int   s  = __shfl_sync(0xffffffffu, sA, rr);
            int   dd = __shfl_sync(0xffffffffu, dA, rr);
            float ea = __shfl_sync(0xffffffffu, eaA, rr);
            __half2 ea2 = __float2half2_rn(ea);
            uint4 ua = *(const uint4*)(g_Ph + (size_t)s  * 256 + c8);
            uint4 ub = *(const uint4*)(g_Ph + (size_t)dd * 256 + 128 + c8);
            uint4 hv;
            {
                __half2 h;
                h = __hadd2(__hadd2(u32_as_h2(ua.x), u32_as_h2(ub.x)), bb[0]);
                hv.x = h2_as_u32(__hmax2(__hfma2(ea2, wc[0], h), zero2));
                h = __hadd2(__hadd2(u32_as_h2(ua.y), u32_as_h2(ub.y)), bb[1]);
                hv.y = h2_as_u32(__hmax2(__hfma2(ea2, wc[1], h), zero2));
                h = __hadd2(__hadd2(u32_as_h2(ua.z), u32_as_h2(ub.z)), bb[2]);
                hv.z = h2_as_u32(__hmax2(__hfma2(ea2, wc[2], h), zero2));
                h = __hadd2(__hadd2(u32_as_h2(ua.w), u32_as_h2(ub.w)), bb[3]);
                hv.w = h2_as_u32(__hmax2(__hfma2(ea2, wc[3], h), zero2));
            }
            *(uint4*)(hbuf + rr * (HS / 2) + (c8 >> 1)) = hv;
        }
        __syncwarp();

        // ---- layer 2: fp16 mma, D[16][32]; A via ldmatrix.x4 ----
        float dacc[4][4];
#pragma unroll
        for (int nt = 0; nt < 4; nt++)
#pragma unroll
            for (int j = 0; j < 4; j++) dacc[nt][j] = 0.f;

#pragma unroll
        for (int kc = 0; kc < 8; kc++) {
            uint32_t a[4];
            ldmatrix_x4(a, lm_base + (uint32_t)kc * 32);
            const uint2* wrow = w2f + kc * 128 + lane;
#pragma unroll
            for (int nt = 0; nt < 4; nt++) {
                uint2 bv = wrow[nt * 32];
                mma_f16(dacc[nt], a, bv.x, bv.y);
            }
        }
        __syncwarp();   // hbuf safe before next tile overwrites

        // ---- layer 3: +b2, relu, *W3, quad-reduce, sigmoid ----
        float acc0 = 0.f, acc1 = 0.f;   // rows base+g and base+g+8
#pragma unroll
        for (int nt = 0; nt < 4; nt++) {
#pragma unroll
            for (int i = 0; i < 2; i++) {
                int col = nt * 8 + 2 * tq + i;
                float w3c = s_w3[col], b2c = s_b2[col];
                acc0 = fmaf(fmaxf(dacc[nt][i]     + b2c, 0.f), w3c, acc0);
                acc1 = fmaf(fmaxf(dacc[nt][2 + i] + b2c, 0.f), w3c, acc1);
            }
        }
        acc0 += __shfl_xor_sync(0xffffffffu, acc0, 1);
        acc0 += __shfl_xor_sync(0xffffffffu, acc0, 2);
        acc1 += __shfl_xor_sync(0xffffffffu, acc1, 1);
        acc1 += __shfl_xor_sync(0xffffffffu, acc1, 2);
        if (tq == 0) {
            int e0 = base + g;
            int e1 = base + g + 8;
            if (e0 < n_edges) {
                float z = acc0 + b3v;
                out[e0] = 1.f / (1.f + __expf(-z));
            }
            if (e1 < n_edges) {
                float z = acc1 + b3v;
                out[e1] = 1.f / (1.f + __expf(-z));
            }
        }
    }
}

// ----------------------------------------------------------------------------
// Launch
// ----------------------------------------------------------------------------
extern "C" void kernel_launch(void* const* d_in, const int* in_sizes, int n_in,
                              void* d_out, int out_size)
{
    const float* x  = (const float*)d_in[0];
    const int*   ei = (const int*)d_in[1];
    const float* ea = (const float*)d_in[2];
    const float* W1 = (const float*)d_in[3];
    const float* b1 = (const float*)d_in[4];
    const float* W2 = (const float*)d_in[5];
    const float* b2 = (const float*)d_in[6];
    const float* W3 = (const float*)d_in[7];
    const float* b3 = (const float*)d_in[8];
    float*       out = (float*)d_out;

    const int n_nodes = in_sizes[0] / HID;     // 100000
    const int n_edges = in_sizes[2];           // 1000000

    static int smem_set = 0;
    if (!smem_set) {
        cudaFuncSetAttribute(node_proj_mma_kernel,
                             cudaFuncAttributeMaxDynamicSharedMemorySize, NP_SMEM_BYTES);
        cudaFuncSetAttribute(edge_mlp_kernel,
                             cudaFuncAttributeMaxDynamicSharedMemorySize, EDGE_SMEM_BYTES);
        smem_set = 1;
    }

    // Kernel 0: pack W1 fragments (L2-hot afterwards)
    pack_w1_kernel<<<32, 256>>>(W1);

    // Kernel 1: node projections (fp16 mma, fp16 output)
    dim3 g1((n_nodes + 127) / 128, 2);
    node_proj_mma_kernel<<<g1, 256, NP_SMEM_BYTES>>>(x, n_nodes);

    // Kernel 2: edge MLP (LDG.128 gather + ldmatrix A-frags)
    const int blocks = 592;
    edge_mlp_kernel<<<blocks, ETHREADS, EDGE_SMEM_BYTES>>>(
        ei, ea, W1, b1, W2, b2, W3, b3, out, n_edges);
}

// round 13
// speedup vs baseline: 1.2724x; 1.1868x over previous
#include <cuda_runtime.h>
#include <cuda_fp16.h>
#include <cstdint>

#define HID 128
#define NNODES 100000

// Node projections, fp16: P[node][0:128] = x@W1[0:128], [128:256] = x@W1[128:256]
__device__ __half g_Ph[(size_t)NNODES * 256];
// W1 packed into fp16 m16n8k16 B-fragment order: [2 halves][8 kc][16 nf][32 lanes] uint2
__device__ uint2 g_W1fh[2 * 8 * 16 * 32];

// ----------------------------------------------------------------------------
// mma helpers (portable: sm_103 PTX target has no tcgen05)
// ----------------------------------------------------------------------------
__device__ __forceinline__ void mma_f16(float* d, const uint32_t* a, uint32_t b0, uint32_t b1) {
    asm volatile(
        "mma.sync.aligned.m16n8k16.row.col.f32.f16.f16.f32 "
        "{%0,%1,%2,%3}, {%4,%5,%6,%7}, {%8,%9}, {%0,%1,%2,%3};"
        : "+f"(d[0]), "+f"(d[1]), "+f"(d[2]), "+f"(d[3])
        : "r"(a[0]), "r"(a[1]), "r"(a[2]), "r"(a[3]), "r"(b0), "r"(b1));
}

__device__ __forceinline__ void ldmatrix_x4(uint32_t* r, uint32_t smem_addr) {
    asm volatile(
        "ldmatrix.sync.aligned.m8n8.x4.shared.b16 {%0,%1,%2,%3}, [%4];"
        : "=r"(r[0]), "=r"(r[1]), "=r"(r[2]), "=r"(r[3])
        : "r"(smem_addr));
}

__device__ __forceinline__ uint32_t h2_as_u32(__half2 h) {
    uint32_t u;
    memcpy(&u, &h, 4);
    return u;
}
__device__ __forceinline__ __half2 u32_as_h2(uint32_t u) {
    __half2 h;
    memcpy(&h, &u, 4);
    return h;
}

// ----------------------------------------------------------------------------
// Kernel 0: pack W1 into fp16 m16n8k16 B-fragment order (once; 64KB, L2-hot).
// ----------------------------------------------------------------------------
__global__ void pack_w1_kernel(const float* __restrict__ W1)
{
    int i = blockIdx.x * blockDim.x + threadIdx.x;
    if (i >= 2 * 8 * 16 * 32) return;
    int o  = i >> 12;
    int kc = (i >> 9) & 7;
    int nf = (i >> 5) & 15;
    int ln = i & 31;
    int g  = ln >> 2, tq = ln & 3;
    int n  = nf * 8 + g;
    int k0 = o * 128 + kc * 16 + 2 * tq;
    __half2 b0 = __floats2half2_rn(W1[(size_t)k0 * HID + n],       W1[(size_t)(k0 + 1) * HID + n]);
    __half2 b1 = __floats2half2_rn(W1[(size_t)(k0 + 8) * HID + n], W1[(size_t)(k0 + 9) * HID + n]);
    g_W1fh[i] = make_uint2(h2_as_u32(b0), h2_as_u32(b1));
}

// ----------------------------------------------------------------------------
// Kernel 1: node projection via fp16 mma. Full K=128 A-tile resident in smem
// (staged ONCE), then both W halves (o=0,1) computed from it -> x read once,
// convert/STS once. Warp tile 64x32 = 4x4 frags per o.
// Row stride 68 words (64 data + 4 pad): frag LDS bank = (4g+tq) mod 32,
// conflict-free.
// ----------------------------------------------------------------------------
#define NPW 68
#define NP_SMEM_BYTES (128 * NPW * 4)

__global__ void __launch_bounds__(256, 2) node_proj_mma_kernel(
    const float* __restrict__ x, int n_nodes)
{
    extern __shared__ uint32_t As[];               // [128 m][68 w] fp16x2

    const int tid  = threadIdx.x;
    const int wid  = tid >> 5;
    const int lane = tid & 31;
    const int g    = lane >> 2;
    const int tq   = lane & 3;
    const int wm   = wid >> 2;       // 0..1
    const int wn   = wid & 3;        // 0..3

    const int bm = blockIdx.x * 128;

    // ---- stage full A tile: 128 rows x 128 halves, one pass ----
    // 2048 quads (4 words = 8 halves each), 8 per thread
#pragma unroll
    for (int p = 0; p < 8; p++) {
        int idx = tid + p * 256;
        int r   = idx >> 4;          // row 0..127
        int q   = idx & 15;          // quad within row
        int grow = bm + r;
        float4 v0 = make_float4(0.f, 0.f, 0.f, 0.f);
        float4 v1 = v0;
        if (grow < n_nodes) {
            const float* xr = x + (size_t)grow * HID + q * 8;
            v0 = *(const float4*)xr;
            v1 = *(const float4*)(xr + 4);
        }
        uint4 t;
        t.x = h2_as_u32(__floats2half2_rn(v0.x, v0.y));
        t.y = h2_as_u32(__floats2half2_rn(v0.z, v0.w));
        t.z = h2_as_u32(__floats2half2_rn(v1.x, v1.y));
        t.w = h2_as_u32(__floats2half2_rn(v1.z, v1.w));
        *(uint4*)(As + r * NPW + q * 4) = t;
    }
    __syncthreads();

    const uint32_t* Ab = As + (wm * 64 + g) * NPW + tq;

#pragma unroll
    for (int o = 0; o < 2; o++) {
        float acc[4][4][4];
#pragma unroll
        for (int a = 0; a < 4; a++)
#pragma unroll
            for (int b = 0; b < 4; b++)
#pragma unroll
                for (int c = 0; c < 4; c++) acc[a][b][c] = 0.f;

        const uint2* __restrict__ wf_base =
            g_W1fh + ((size_t)o * 8 * 16 + wn * 4) * 32 + lane;

#pragma unroll
        for (int kc = 0; kc < 8; kc++) {          // 8 k16 chunks
            uint2 bfr[4];
            const uint2* wf = wf_base + (size_t)kc * 16 * 32;
#pragma unroll
            for (int nf = 0; nf < 4; nf++) bfr[nf] = wf[nf * 32];

            uint32_t afr[4][4];
#pragma unroll
            for (int mf = 0; mf < 4; mf++) {
                const uint32_t* ap = Ab + mf * 16 * NPW + kc * 8;
                afr[mf][0] = ap[0];
                afr[mf][1] = ap[8 * NPW];
                afr[mf][2] = ap[4];
                afr[mf][3] = ap[8 * NPW + 4];
            }
#pragma unroll
            for (int mf = 0; mf < 4; mf++)
#pragma unroll
                for (int nf = 0; nf < 4; nf++)
                    mma_f16(acc[mf][nf], afr[mf], bfr[nf].x, bfr[nf].y);
        }

        // epilogue: fp16 P half o
#pragma unroll
        for (int mf = 0; mf < 4; mf++) {
            int r0g = bm + wm * 64 + mf * 16 + g;
#pragma unroll
            for (int nf = 0; nf < 4; nf++) {
                int col = o * 128 + wn * 32 + nf * 8 + 2 * tq;
                if (r0g < n_nodes)
                    *(__half2*)(g_Ph + (size_t)r0g * 256 + col) =
                        __floats2half2_rn(acc[mf][nf][0], acc[mf][nf][1]);
                if (r0g + 8 < n_nodes)
                    *(__half2*)(g_Ph + (size_t)(r0g + 8) * 256 + col) =
                        __floats2half2_rn(acc[mf][nf][2], acc[mf][nf][3]);
            }
        }
    }
}

// ----------------------------------------------------------------------------
// Kernel 2: edge MLP (unchanged from R12 — protect the win).
// 8 warps/block, 16-edge tiles/warp. LDG.128 gather 2 edges/iter;
// A-fragments via ldmatrix.x4.
// ----------------------------------------------------------------------------
#define EWARPS 8
#define ETHREADS (EWARPS * 32)
#define HS 136                          // halves per hbuf row (68 words)
#define HBUF_WORDS (16 * (HS / 2))
#define W2F_COUNT (8 * 4 * 32)          // 1024 uint2 = 8KB
#define EDGE_SMEM_BYTES (W2F_COUNT * 8 + 256 + EWARPS * HBUF_WORDS * 4)

__global__ void __launch_bounds__(ETHREADS, 4) edge_mlp_kernel(
    const int*   __restrict__ edge_index,   // [2*E]: src then dst
    const float* __restrict__ eattr,        // [E]
    const float* __restrict__ W1,           // [257*128], row 256 = w1c
    const float* __restrict__ b1,           // [128]
    const float* __restrict__ W2,           // [128*32]
    const float* __restrict__ b2,           // [32]
    const float* __restrict__ W3,           // [32]
    const float* __restrict__ b3,           // [1]
    float*       __restrict__ out,          // [E]
    int n_edges)
{
    extern __shared__ char smem[];
    uint2* __restrict__ w2f  = (uint2*)smem;                       // fp16 B frags
    float* __restrict__ s_b2 = (float*)(smem + W2F_COUNT * 8);     // [32]
    float* __restrict__ s_w3 = s_b2 + 32;                          // [32]
    uint32_t* __restrict__ hb_all = (uint32_t*)(smem + W2F_COUNT * 8 + 256);

    const int tid  = threadIdx.x;
    const int wid  = tid >> 5;
    const int lane = tid & 31;
    const int g    = lane >> 2;
    const int tq   = lane & 3;
    const int hl   = lane >> 4;          // half-warp: which of 2 edges per iter
    const int l16  = lane & 15;
    uint32_t* __restrict__ hbuf = hb_all + wid * HBUF_WORDS;

    // --- pack W2 into fp16 m16n8k16 B-fragment order ---
    for (int i = tid; i < W2F_COUNT; i += ETHREADS) {
        int kc = i >> 7;
        int nt = (i >> 5) & 3;
        int ln = i & 31;
        int col = nt * 8 + (ln >> 2);
        int k0  = kc * 16 + (ln & 3) * 2;
        __half2 lo = __floats2half2_rn(W2[k0 * 32 + col],       W2[(k0 + 1) * 32 + col]);
        __half2 hi = __floats2half2_rn(W2[(k0 + 8) * 32 + col], W2[(k0 + 9) * 32 + col]);
        w2f[i] = make_uint2(h2_as_u32(lo), h2_as_u32(hi));
    }
    if (tid < 32) { s_b2[tid] = b2[tid]; s_w3[tid] = W3[tid]; }
    __syncthreads();

    // --- per-lane layer-1 constants: this lane handles h cols c8..c8+7 ---
    const int c8 = l16 * 8;
    __half2 wc[4], bb[4];
    {
        const float* wrow = W1 + 256 * HID + c8;
#pragma unroll
        for (int j = 0; j < 4; j++) {
            wc[j] = __floats2half2_rn(wrow[2 * j], wrow[2 * j + 1]);
            bb[j] = __floats2half2_rn(b1[c8 + 2 * j], b1[c8 + 2 * j + 1]);
        }
    }
    const __half2 zero2 = __floats2half2_rn(0.f, 0.f);
    const float  b3v = b3[0];

    // ldmatrix base address (A-frag): row = lane&15, k-offset = (lane>>4)*8 halves
    const uint32_t hb_smem = (uint32_t)__cvta_generic_to_shared(hbuf);
    const uint32_t lm_base = hb_smem + (uint32_t)l16 * (HS / 2) * 4 + (uint32_t)hl * 16;

    const int* __restrict__ src = edge_index;
    const int* __restrict__ dst = edge_index + n_edges;

    const int gw = blockIdx.x * EWARPS + wid;
    const int nwarps = gridDim.x * EWARPS;
    const int ntiles = (n_edges + 15) >> 4;

    for (int t = gw; t < ntiles; t += nwarps) {
        const int base = t << 4;

        // ---- stage edge data (lanes 0..15), broadcast via shfl ----
        int sA = 0, dA = 0;
        float eaA = 0.f;
        if (lane < 16) {
            int e = base + lane;
            if (e < n_edges) { sA = src[e]; dA = dst[e]; eaA = eattr[e]; }
        }

        // ---- layer 1: LDG.128 gather, 2 edges per iteration ----
#pragma unroll
        for (int it = 0; it < 8; it++) {
            const int rr = 2 * it + hl;
            int   s  = __shfl_sync(0xffffffffu, sA, rr);
            int   dd = __shfl_sync(0xffffffffu, dA, rr);
            float ea = __shfl_sync(0xffffffffu, eaA, rr);
            __half2 ea2 = __float2half2_rn(ea);
            uint4 ua = *(const uint4*)(g_Ph + (size_t)s  * 256 + c8);
            uint4 ub = *(const uint4*)(g_Ph + (size_t)dd * 256 + 128 + c8);
            uint4 hv;
            {
                __half2 h;
                h = __hadd2(__hadd2(u32_as_h2(ua.x), u32_as_h2(ub.x)), bb[0]);
                hv.x = h2_as_u32(__hmax2(__hfma2(ea2, wc[0], h), zero2));
                h = __hadd2(__hadd2(u32_as_h2(ua.y), u32_as_h2(ub.y)), bb[1]);
                hv.y = h2_as_u32(__hmax2(__hfma2(ea2, wc[1], h), zero2));
                h = __hadd2(__hadd2(u32_as_h2(ua.z), u32_as_h2(ub.z)), bb[2]);
                hv.z = h2_as_u32(__hmax2(__hfma2(ea2, wc[2], h), zero2));
                h = __hadd2(__hadd2(u32_as_h2(ua.w), u32_as_h2(ub.w)), bb[3]);
                hv.w = h2_as_u32(__hmax2(__hfma2(ea2, wc[3], h), zero2));
            }
            *(uint4*)(hbuf + rr * (HS / 2) + (c8 >> 1)) = hv;
        }
        __syncwarp();

        // ---- layer 2: fp16 mma, D[16][32]; A via ldmatrix.x4 ----
        float dacc[4][4];
#pragma unroll
        for (int nt = 0; nt < 4; nt++)
#pragma unroll
            for (int j = 0; j < 4; j++) dacc[nt][j] = 0.f;

#pragma unroll
        for (int kc = 0; kc < 8; kc++) {
            uint32_t a[4];
            ldmatrix_x4(a, lm_base + (uint32_t)kc * 32);
            const uint2* wrow = w2f + kc * 128 + lane;
#pragma unroll
            for (int nt = 0; nt < 4; nt++) {
                uint2 bv = wrow[nt * 32];
                mma_f16(dacc[nt], a, bv.x, bv.y);
            }
        }
        __syncwarp();   // hbuf safe before next tile overwrites

        // ---- layer 3: +b2, relu, *W3, quad-reduce, sigmoid ----
        float acc0 = 0.f, acc1 = 0.f;   // rows base+g and base+g+8
#pragma unroll
        for (int nt = 0; nt < 4; nt++) {
#pragma unroll
            for (int i = 0; i < 2; i++) {
                int col = nt * 8 + 2 * tq + i;
                float w3c = s_w3[col], b2c = s_b2[col];
                acc0 = fmaf(fmaxf(dacc[nt][i]     + b2c, 0.f), w3c, acc0);
                acc1 = fmaf(fmaxf(dacc[nt][2 + i] + b2c, 0.f), w3c, acc1);
            }
        }
        acc0 += __shfl_xor_sync(0xffffffffu, acc0, 1);
        acc0 += __shfl_xor_sync(0xffffffffu, acc0, 2);
        acc1 += __shfl_xor_sync(0xffffffffu, acc1, 1);
        acc1 += __shfl_xor_sync(0xffffffffu, acc1, 2);
        if (tq == 0) {
            int e0 = base + g;
            int e1 = base + g + 8;
            if (e0 < n_edges) {
                float z = acc0 + b3v;
                out[e0] = 1.f / (1.f + __expf(-z));
            }
            if (e1 < n_edges) {
                float z = acc1 + b3v;
                out[e1] = 1.f / (1.f + __expf(-z));
            }
        }
    }
}

// ----------------------------------------------------------------------------
// Launch
// ----------------------------------------------------------------------------
extern "C" void kernel_launch(void* const* d_in, const int* in_sizes, int n_in,
                              void* d_out, int out_size)
{
    const float* x  = (const float*)d_in[0];
    const int*   ei = (const int*)d_in[1];
    const float* ea = (const float*)d_in[2];
    const float* W1 = (const float*)d_in[3];
    const float* b1 = (const float*)d_in[4];
    const float* W2 = (const float*)d_in[5];
    const float* b2 = (const float*)d_in[6];
    const float* W3 = (const float*)d_in[7];
    const float* b3 = (const float*)d_in[8];
    float*       out = (float*)d_out;

    const int n_nodes = in_sizes[0] / HID;     // 100000
    const int n_edges = in_sizes[2];           // 1000000

    static int smem_set = 0;
    if (!smem_set) {
        cudaFuncSetAttribute(node_proj_mma_kernel,
                             cudaFuncAttributeMaxDynamicSharedMemorySize, NP_SMEM_BYTES);
        cudaFuncSetAttribute(edge_mlp_kernel,
                             cudaFuncAttributeMaxDynamicSharedMemorySize, EDGE_SMEM_BYTES);
        smem_set = 1;
    }

    // Kernel 0: pack W1 fragments (L2-hot afterwards)
    pack_w1_kernel<<<32, 256>>>(W1);

    // Kernel 1: node projections (both halves per block, x read once)
    const int g1 = (n_nodes + 127) / 128;
    node_proj_mma_kernel<<<g1, 256, NP_SMEM_BYTES>>>(x, n_nodes);

    // Kernel 2: edge MLP (LDG.128 gather + ldmatrix A-frags)
    const int blocks = 592;
    edge_mlp_kernel<<<blocks, ETHREADS, EDGE_SMEM_BYTES>>>(
        ei, ea, W1, b1, W2, b2, W3, b3, out, n_edges);
}

// round 14
// speedup vs baseline: 1.3077x; 1.0277x over previous
#include <cuda_runtime.h>
#include <cuda_fp16.h>
#include <cstdint>

#define HID 128
#define NNODES 100000

// Node projections, fp16: P[node][0:128] = x@W1[0:128], [128:256] = x@W1[128:256]
__device__ __half g_Ph[(size_t)NNODES * 256];
// W1 packed into fp16 m16n8k16 B-fragment order: [2 halves][8 kc][16 nf][32 lanes] uint2
__device__ uint2 g_W1fh[2 * 8 * 16 * 32];

// ----------------------------------------------------------------------------
// mma helpers (portable: sm_103 PTX target has no tcgen05)
// ----------------------------------------------------------------------------
__device__ __forceinline__ void mma_f16(float* d, const uint32_t* a, uint32_t b0, uint32_t b1) {
    asm volatile(
        "mma.sync.aligned.m16n8k16.row.col.f32.f16.f16.f32 "
        "{%0,%1,%2,%3}, {%4,%5,%6,%7}, {%8,%9}, {%0,%1,%2,%3};"
        : "+f"(d[0]), "+f"(d[1]), "+f"(d[2]), "+f"(d[3])
        : "r"(a[0]), "r"(a[1]), "r"(a[2]), "r"(a[3]), "r"(b0), "r"(b1));
}

__device__ __forceinline__ void ldmatrix_x4(uint32_t* r, uint32_t smem_addr) {
    asm volatile(
        "ldmatrix.sync.aligned.m8n8.x4.shared.b16 {%0,%1,%2,%3}, [%4];"
        : "=r"(r[0]), "=r"(r[1]), "=r"(r[2]), "=r"(r[3])
        : "r"(smem_addr));
}

__device__ __forceinline__ uint32_t h2_as_u32(__half2 h) {
    uint32_t u;
    memcpy(&u, &h, 4);
    return u;
}
__device__ __forceinline__ __half2 u32_as_h2(uint32_t u) {
    __half2 h;
    memcpy(&h, &u, 4);
    return h;
}

// ----------------------------------------------------------------------------
// Kernel 0: pack W1 into fp16 m16n8k16 B-fragment order (once; 64KB, L2-hot).
// ----------------------------------------------------------------------------
__global__ void pack_w1_kernel(const float* __restrict__ W1)
{
    int i = blockIdx.x * blockDim.x + threadIdx.x;
    if (i >= 2 * 8 * 16 * 32) return;
    int o  = i >> 12;
    int kc = (i >> 9) & 7;
    int nf = (i >> 5) & 15;
    int ln = i & 31;
    int g  = ln >> 2, tq = ln & 3;
    int n  = nf * 8 + g;
    int k0 = o * 128 + kc * 16 + 2 * tq;
    __half2 b0 = __floats2half2_rn(W1[(size_t)k0 * HID + n],       W1[(size_t)(k0 + 1) * HID + n]);
    __half2 b1 = __floats2half2_rn(W1[(size_t)(k0 + 8) * HID + n], W1[(size_t)(k0 + 9) * HID + n]);
    g_W1fh[i] = make_uint2(h2_as_u32(b0), h2_as_u32(b1));
}

// ----------------------------------------------------------------------------
// Kernel 1: node projection via fp16 mma. Full K=128 A-tile resident in smem
// (staged ONCE), then both W halves (o=0,1) computed from it.
// ----------------------------------------------------------------------------
#define NPW 68
#define NP_SMEM_BYTES (128 * NPW * 4)

__global__ void __launch_bounds__(256, 2) node_proj_mma_kernel(
    const float* __restrict__ x, int n_nodes)
{
    extern __shared__ uint32_t As[];               // [128 m][68 w] fp16x2

    const int tid  = threadIdx.x;
    const int wid  = tid >> 5;
    const int lane = tid & 31;
    const int g    = lane >> 2;
    const int tq   = lane & 3;
    const int wm   = wid >> 2;       // 0..1
    const int wn   = wid & 3;        // 0..3

    const int bm = blockIdx.x * 128;

    // ---- stage full A tile: 128 rows x 128 halves, one pass ----
#pragma unroll
    for (int p = 0; p < 8; p++) {
        int idx = tid + p * 256;
        int r   = idx >> 4;
        int q   = idx & 15;
        int grow = bm + r;
        float4 v0 = make_float4(0.f, 0.f, 0.f, 0.f);
        float4 v1 = v0;
        if (grow < n_nodes) {
            const float* xr = x + (size_t)grow * HID + q * 8;
            v0 = *(const float4*)xr;
            v1 = *(const float4*)(xr + 4);
        }
        uint4 t;
        t.x = h2_as_u32(__floats2half2_rn(v0.x, v0.y));
        t.y = h2_as_u32(__floats2half2_rn(v0.z, v0.w));
        t.z = h2_as_u32(__floats2half2_rn(v1.x, v1.y));
        t.w = h2_as_u32(__floats2half2_rn(v1.z, v1.w));
        *(uint4*)(As + r * NPW + q * 4) = t;
    }
    __syncthreads();

    const uint32_t* Ab = As + (wm * 64 + g) * NPW + tq;

#pragma unroll
    for (int o = 0; o < 2; o++) {
        float acc[4][4][4];
#pragma unroll
        for (int a = 0; a < 4; a++)
#pragma unroll
            for (int b = 0; b < 4; b++)
#pragma unroll
                for (int c = 0; c < 4; c++) acc[a][b][c] = 0.f;

        const uint2* __restrict__ wf_base =
            g_W1fh + ((size_t)o * 8 * 16 + wn * 4) * 32 + lane;

#pragma unroll
        for (int kc = 0; kc < 8; kc++) {
            uint2 bfr[4];
            const uint2* wf = wf_base + (size_t)kc * 16 * 32;
#pragma unroll
            for (int nf = 0; nf < 4; nf++) bfr[nf] = wf[nf * 32];

            uint32_t afr[4][4];
#pragma unroll
            for (int mf = 0; mf < 4; mf++) {
                const uint32_t* ap = Ab + mf * 16 * NPW + kc * 8;
                afr[mf][0] = ap[0];
                afr[mf][1] = ap[8 * NPW];
                afr[mf][2] = ap[4];
                afr[mf][3] = ap[8 * NPW + 4];
            }
#pragma unroll
            for (int mf = 0; mf < 4; mf++)
#pragma unroll
                for (int nf = 0; nf < 4; nf++)
                    mma_f16(acc[mf][nf], afr[mf], bfr[nf].x, bfr[nf].y);
        }

        // epilogue: fp16 P half o
#pragma unroll
        for (int mf = 0; mf < 4; mf++) {
            int r0g = bm + wm * 64 + mf * 16 + g;
#pragma unroll
            for (int nf = 0; nf < 4; nf++) {
                int col = o * 128 + wn * 32 + nf * 8 + 2 * tq;
                if (r0g < n_nodes)
                    *(__half2*)(g_Ph + (size_t)r0g * 256 + col) =
                        __floats2half2_rn(acc[mf][nf][0], acc[mf][nf][1]);
                if (r0g + 8 < n_nodes)
                    *(__half2*)(g_Ph + (size_t)(r0g + 8) * 256 + col) =
                        __floats2half2_rn(acc[mf][nf][2], acc[mf][nf][3]);
            }
        }
    }
}

// ----------------------------------------------------------------------------
// Kernel 2: edge MLP. 8 warps/block, 16-edge tiles/warp, LDG.128 gather
// (2 edges/iter), A-frags via ldmatrix.x4, B-frags via ldmatrix.x4 from a
// w2f buffer packed in ldmatrix row order (register values identical to the
// previous LDS.64 path). Next-tile edge indices prefetched under the MMA.
// ----------------------------------------------------------------------------
#define EWARPS 8
#define ETHREADS (EWARPS * 32)
#define HS 136                          // halves per hbuf row (68 words)
#define HBUF_WORDS (16 * (HS / 2))
// w2f ldmatrix layout: [8 kc][8 matrices(128B)] = 8KB
#define W2F_BYTES 8192
#define EDGE_SMEM_BYTES (W2F_BYTES + 256 + EWARPS * HBUF_WORDS * 4)

__global__ void __launch_bounds__(ETHREADS, 4) edge_mlp_kernel(
    const int*   __restrict__ edge_index,   // [2*E]: src then dst
    const float* __restrict__ eattr,        // [E]
    const float* __restrict__ W1,           // [257*128], row 256 = w1c
    const float* __restrict__ b1,           // [128]
    const float* __restrict__ W2,           // [128*32]
    const float* __restrict__ b2,           // [32]
    const float* __restrict__ W3,           // [32]
    const float* __restrict__ b3,           // [1]
    float*       __restrict__ out,          // [E]
    int n_edges)
{
    extern __shared__ char smem[];
    uint32_t* __restrict__ w2f = (uint32_t*)smem;                  // ldmatrix-packed
    float* __restrict__ s_b2 = (float*)(smem + W2F_BYTES);         // [32]
    float* __restrict__ s_w3 = s_b2 + 32;                          // [32]
    uint32_t* __restrict__ hb_all = (uint32_t*)(smem + W2F_BYTES + 256);

    const int tid  = threadIdx.x;
    const int wid  = tid >> 5;
    const int lane = tid & 31;
    const int g    = lane >> 2;
    const int tq   = lane & 3;
    const int hl   = lane >> 4;          // half-warp: which of 2 edges per iter
    const int l16  = lane & 15;
    uint32_t* __restrict__ hbuf = hb_all + wid * HBUF_WORDS;

    // --- pack W2 into ldmatrix row order ---
    // word i = [kc(8)][m(8)][g(8)][ep(4)]; m = nt*2 + hb.
    // matrix M[g][e] = W2[kc*16 + hb*8 + e][nt*8 + g], words pack e pairs.
    for (int i = tid; i < 2048; i += ETHREADS) {
        int kc = i >> 8;
        int m  = (i >> 5) & 7;
        int gg = (i >> 2) & 7;
        int ep = i & 3;
        int nt = m >> 1, hb = m & 1;
        int k  = kc * 16 + hb * 8 + 2 * ep;
        int col = nt * 8 + gg;
        __half2 v = __floats2half2_rn(W2[k * 32 + col], W2[(k + 1) * 32 + col]);
        w2f[i] = h2_as_u32(v);
    }
    if (tid < 32) { s_b2[tid] = b2[tid]; s_w3[tid] = W3[tid]; }
    __syncthreads();

    // --- per-lane layer-1 constants: this lane handles h cols c8..c8+7 ---
    const int c8 = l16 * 8;
    __half2 wc[4], bb[4];
    {
        const float* wrow = W1 + 256 * HID + c8;
#pragma unroll
        for (int j = 0; j < 4; j++) {
            wc[j] = __floats2half2_rn(wrow[2 * j], wrow[2 * j + 1]);
            bb[j] = __floats2half2_rn(b1[c8 + 2 * j], b1[c8 + 2 * j + 1]);
        }
    }
    const __half2 zero2 = __floats2half2_rn(0.f, 0.f);
    const float  b3v = b3[0];

    // ldmatrix base addresses
    const uint32_t hb_smem = (uint32_t)__cvta_generic_to_shared(hbuf);
    const uint32_t lmA_base = hb_smem + (uint32_t)l16 * (HS / 2) * 4 + (uint32_t)hl * 16;
    const uint32_t w2_smem = (uint32_t)__cvta_generic_to_shared(w2f);
    const uint32_t lmB_base = w2_smem + (uint32_t)lane * 16;

    const int* __restrict__ src = edge_index;
    const int* __restrict__ dst = edge_index + n_edges;

    const int gw = blockIdx.x * EWARPS + wid;
    const int nwarps = gridDim.x * EWARPS;
    const int ntiles = (n_edges + 15) >> 4;

    // ---- prologue: stage first tile's edge data ----
    int sA = 0, dA = 0;
    float eaA = 0.f;
    if (lane < 16 && gw < ntiles) {
        int e = (gw << 4) + lane;
        if (e < n_edges) { sA = src[e]; dA = dst[e]; eaA = eattr[e]; }
    }

    for (int t = gw; t < ntiles; t += nwarps) {
        const int base = t << 4;

        // ---- layer 1: LDG.128 gather, 2 edges per iteration ----
#pragma unroll
        for (int it = 0; it < 8; it++) {
            const int rr = 2 * it + hl;
            int   s  = __shfl_sync(0xffffffffu, sA, rr);
            int   dd = __shfl_sync(0xffffffffu, dA, rr);
            float ea = __shfl_sync(0xffffffffu, eaA, rr);
            __half2 ea2 = __float2half2_rn(ea);
            uint4 ua = *(const uint4*)(g_Ph + (size_t)s  * 256 + c8);
            uint4 ub = *(const uint4*)(g_Ph + (size_t)dd * 256 + 128 + c8);
            uint4 hv;
            {
                __half2 h;
                h = __hadd2(__hadd2(u32_as_h2(ua.x), u32_as_h2(ub.x)), bb[0]);
                hv.x = h2_as_u32(__hmax2(__hfma2(ea2, wc[0], h), zero2));
                h = __hadd2(__hadd2(u32_as_h2(ua.y), u32_as_h2(ub.y)), bb[1]);
                hv.y = h2_as_u32(__hmax2(__hfma2(ea2, wc[1], h), zero2));
                h = __hadd2(__hadd2(u32_as_h2(ua.z), u32_as_h2(ub.z)), bb[2]);
                hv.z = h2_as_u32(__hmax2(__hfma2(ea2, wc[2], h), zero2));
                h = __hadd2(__hadd2(u32_as_h2(ua.w), u32_as_h2(ub.w)), bb[3]);
                hv.w = h2_as_u32(__hmax2(__hfma2(ea2, wc[3], h), zero2));
            }
            *(uint4*)(hbuf + rr * (HS / 2) + (c8 >> 1)) = hv;
        }
        __syncwarp();

        // ---- prefetch next tile's edge indices (hidden under MMA) ----
        int sN = 0, dN = 0;
        float eaN = 0.f;
        {
            int t2 = t + nwarps;
            if (lane < 16 && t2 < ntiles) {
                int e = (t2 << 4) + lane;
                if (e < n_edges) { sN = src[e]; dN = dst[e]; eaN = eattr[e]; }
            }
        }

        // ---- layer 2: fp16 mma; A and B both via ldmatrix.x4 ----
        float dacc[4][4];
#pragma unroll
        for (int nt = 0; nt < 4; nt++)
#pragma unroll
            for (int j = 0; j < 4; j++) dacc[nt][j] = 0.f;

#pragma unroll
        for (int kc = 0; kc < 8; kc++) {
            uint32_t a[4];
            ldmatrix_x4(a, lmA_base + (uint32_t)kc * 32);
            uint32_t b01[4], b23[4];
            ldmatrix_x4(b01, lmB_base + (uint32_t)kc * 1024);
            ldmatrix_x4(b23, lmB_base + (uint32_t)kc * 1024 + 512);
            mma_f16(dacc[0], a, b01[0], b01[1]);
            mma_f16(dacc[1], a, b01[2], b01[3]);
            mma_f16(dacc[2], a, b23[0], b23[1]);
            mma_f16(dacc[3], a, b23[2], b23[3]);
        }
        __syncwarp();   // hbuf safe before next tile overwrites

        // ---- layer 3: +b2, relu, *W3, quad-reduce, sigmoid ----
        float acc0 = 0.f, acc1 = 0.f;   // rows base+g and base+g+8
#pragma unroll
        for (int nt = 0; nt < 4; nt++) {
#pragma unroll
            for (int i = 0; i < 2; i++) {
                int col = nt * 8 + 2 * tq + i;
                float w3c = s_w3[col], b2c = s_b2[col];
                acc0 = fmaf(fmaxf(dacc[nt][i]     + b2c, 0.f), w3c, acc0);
                acc1 = fmaf(fmaxf(dacc[nt][2 + i] + b2c, 0.f), w3c, acc1);
            }
        }
        acc0 += __shfl_xor_sync(0xffffffffu, acc0, 1);
        acc0 += __shfl_xor_sync(0xffffffffu, acc0, 2);
        acc1 += __shfl_xor_sync(0xffffffffu, acc1, 1);
        acc1 += __shfl_xor_sync(0xffffffffu, acc1, 2);
        if (tq == 0) {
            int e0 = base + g;
            int e1 = base + g + 8;
            if (e0 < n_edges) {
                float z = acc0 + b3v;
                out[e0] = 1.f / (1.f + __expf(-z));
            }
            if (e1 < n_edges) {
                float z = acc1 + b3v;
                out[e1] = 1.f / (1.f + __expf(-z));
            }
        }

        sA = sN; dA = dN; eaA = eaN;
    }
}

// ----------------------------------------------------------------------------
// Launch
// ----------------------------------------------------------------------------
extern "C" void kernel_launch(void* const* d_in, const int* in_sizes, int n_in,
                              void* d_out, int out_size)
{
    const float* x  = (const float*)d_in[0];
    const int*   ei = (const int*)d_in[1];
    const float* ea = (const float*)d_in[2];
    const float* W1 = (const float*)d_in[3];
    const float* b1 = (const float*)d_in[4];
    const float* W2 = (const float*)d_in[5];
    const float* b2 = (const float*)d_in[6];
    const float* W3 = (const float*)d_in[7];
    const float* b3 = (const float*)d_in[8];
    float*       out = (float*)d_out;

    const int n_nodes = in_sizes[0] / HID;     // 100000
    const int n_edges = in_sizes[2];           // 1000000

    static int smem_set = 0;
    if (!smem_set) {
        cudaFuncSetAttribute(node_proj_mma_kernel,
                             cudaFuncAttributeMaxDynamicSharedMemorySize, NP_SMEM_BYTES);
        cudaFuncSetAttribute(edge_mlp_kernel,
                             cudaFuncAttributeMaxDynamicSharedMemorySize, EDGE_SMEM_BYTES);
        smem_set = 1;
    }

    // Kernel 0: pack W1 fragments (L2-hot afterwards)
    pack_w1_kernel<<<32, 256>>>(W1);

    // Kernel 1: node projections (both halves per block, x read once)
    const int g1 = (n_nodes + 127) / 128;
    node_proj_mma_kernel<<<g1, 256, NP_SMEM_BYTES>>>(x, n_nodes);

    // Kernel 2: edge MLP (ldmatrix A+B, index prefetch)
    const int blocks = 592;
    edge_mlp_kernel<<<blocks, ETHREADS, EDGE_SMEM_BYTES>>>(
        ei, ea, W1, b1, W2, b2, W3, b3, out, n_edges);
}